// round 2
// baseline (speedup 1.0000x reference)
#include <cuda_runtime.h>
#include <cuda_bf16.h>
#include <math.h>

// Problem constants
#define B_ 4
#define N_ 2048
#define C_ 512
#define H_ 8
#define DH 64
#define M_ (B_ * N_)          // 8192
#define NQKV (3 * C_)         // 1536

// Scratch (device globals; no allocation allowed)
__device__ float g_Q[B_ * H_ * N_ * DH];
__device__ float g_K[B_ * H_ * N_ * DH];
__device__ float g_V[B_ * H_ * N_ * DH];
__device__ float g_O[B_ * N_ * C_];
__device__ float g_cos[B_ * N_ * (DH / 2)];
__device__ float g_sin[B_ * N_ * (DH / 2)];

// ---------------------------------------------------------------------------
// Kernel 0: RoPE cos/sin tables.  pos = rint(times*30); inv_freq = 10000^{-i/32}
// ---------------------------------------------------------------------------
__global__ void rope_table_kernel(const float* __restrict__ times) {
    int idx = blockIdx.x * 256 + threadIdx.x;
    if (idx >= B_ * N_ * 32) return;
    int i = idx & 31;
    int bn = idx >> 5;
    float pos = rintf(times[bn] * 30.0f);
    float inv_freq = powf(10000.0f, -(float)i / 32.0f);
    float f = pos * inv_freq;
    float s, c;
    sincosf(f, &s, &c);
    g_cos[idx] = c;
    g_sin[idx] = s;
}

// ---------------------------------------------------------------------------
// Kernel 1: QKV GEMM (M=8192, N=1536, K=512) + RoPE epilogue + scatter
//   out[m][n] = sum_k x[m][k] * Wqkv[n][k]
//   col n = s*512 + h*64 + d ;  s=0:q(rope), 1:k(rope), 2:v
//   BM=BN=128, BK=16, 256 threads, 8x8 micro-tile
// ---------------------------------------------------------------------------
__global__ __launch_bounds__(256) void gemm_qkv_kernel(const float* __restrict__ x,
                                                       const float* __restrict__ W) {
    __shared__ float As[16][132];
    __shared__ float Bs[16][132];
    int tid = threadIdx.x;
    int tx = tid & 15, ty = tid >> 4;
    int m0 = blockIdx.y * 128;
    int n0 = blockIdx.x * 128;
    int lr = tid >> 2;           // 0..63
    int lk = (tid & 3) << 2;     // 0,4,8,12

    float acc[8][8];
#pragma unroll
    for (int i = 0; i < 8; ++i)
#pragma unroll
        for (int j = 0; j < 8; ++j) acc[i][j] = 0.0f;

    for (int k0 = 0; k0 < 512; k0 += 16) {
        float4 a0 = *(const float4*)&x[(size_t)(m0 + lr) * 512 + k0 + lk];
        float4 a1 = *(const float4*)&x[(size_t)(m0 + lr + 64) * 512 + k0 + lk];
        float4 b0 = *(const float4*)&W[(size_t)(n0 + lr) * 512 + k0 + lk];
        float4 b1 = *(const float4*)&W[(size_t)(n0 + lr + 64) * 512 + k0 + lk];
        As[lk + 0][lr] = a0.x; As[lk + 1][lr] = a0.y; As[lk + 2][lr] = a0.z; As[lk + 3][lr] = a0.w;
        As[lk + 0][lr + 64] = a1.x; As[lk + 1][lr + 64] = a1.y; As[lk + 2][lr + 64] = a1.z; As[lk + 3][lr + 64] = a1.w;
        Bs[lk + 0][lr] = b0.x; Bs[lk + 1][lr] = b0.y; Bs[lk + 2][lr] = b0.z; Bs[lk + 3][lr] = b0.w;
        Bs[lk + 0][lr + 64] = b1.x; Bs[lk + 1][lr + 64] = b1.y; Bs[lk + 2][lr + 64] = b1.z; Bs[lk + 3][lr + 64] = b1.w;
        __syncthreads();
#pragma unroll
        for (int k = 0; k < 16; ++k) {
            float4 ra0 = *(const float4*)&As[k][ty * 8];
            float4 ra1 = *(const float4*)&As[k][ty * 8 + 4];
            float4 rb0 = *(const float4*)&Bs[k][tx * 4];
            float4 rb1 = *(const float4*)&Bs[k][tx * 4 + 64];
            float ra[8] = {ra0.x, ra0.y, ra0.z, ra0.w, ra1.x, ra1.y, ra1.z, ra1.w};
            float rb[8] = {rb0.x, rb0.y, rb0.z, rb0.w, rb1.x, rb1.y, rb1.z, rb1.w};
#pragma unroll
            for (int i = 0; i < 8; ++i)
#pragma unroll
                for (int j = 0; j < 8; ++j) acc[i][j] += ra[i] * rb[j];
        }
        __syncthreads();
    }

    // Epilogue: RoPE on q,k cols; scatter into [B,H,N,Dh]
#pragma unroll
    for (int i = 0; i < 8; ++i) {
        int m = m0 + ty * 8 + i;          // m = b*2048 + n
        int b = m >> 11;
        int n = m & 2047;
#pragma unroll
        for (int g = 0; g < 2; ++g) {
            int cb = n0 + tx * 4 + g * 64;    // 4 consecutive cols, pair-aligned
            int s = cb >> 9;
            int h = (cb >> 6) & 7;
            int d = cb & 63;
            size_t base = ((size_t)((b * 8 + h) * 2048 + n)) * 64 + d;
            float v0 = acc[i][g * 4 + 0];
            float v1 = acc[i][g * 4 + 1];
            float v2 = acc[i][g * 4 + 2];
            float v3 = acc[i][g * 4 + 3];
            if (s == 2) {
                g_V[base + 0] = v0; g_V[base + 1] = v1;
                g_V[base + 2] = v2; g_V[base + 3] = v3;
            } else {
                int i2 = d >> 1;
                float c0 = g_cos[m * 32 + i2],     s0 = g_sin[m * 32 + i2];
                float c1 = g_cos[m * 32 + i2 + 1], s1 = g_sin[m * 32 + i2 + 1];
                float* dst = (s == 0) ? g_Q : g_K;
                dst[base + 0] = v0 * c0 - v1 * s0;
                dst[base + 1] = v0 * s0 + v1 * c0;
                dst[base + 2] = v2 * c1 - v3 * s1;
                dst[base + 3] = v2 * s1 + v3 * c1;
            }
        }
    }
}

// ---------------------------------------------------------------------------
// Kernel 2: flash attention.  grid (32 q-tiles, 32 b*h), 256 threads.
// Q tile 64x64, loop over 32 KV tiles of 64. Online softmax.
// Ks buffer reused for P after S-compute. Dynamic smem = 51200 B.
// ---------------------------------------------------------------------------
__global__ __launch_bounds__(256) void attn_kernel(const float* __restrict__ mask) {
    extern __shared__ float sm[];
    float* Qs = sm;                 // 64*64   (stride 64, broadcast reads)
    float* Ks = sm + 4096;          // 64*68   (also P after exp)
    float* Vs = Ks + 64 * 68;       // 64*68

    int tid = threadIdx.x;
    int tx = tid & 15, ty = tid >> 4;
    int bh = blockIdx.y;
    int b = bh >> 3, h = bh & 7;
    int q0 = blockIdx.x * 64;

    const float* Qg = g_Q + ((size_t)bh * 2048 + q0) * 64;
    const float* Kgb = g_K + (size_t)bh * 2048 * 64;
    const float* Vgb = g_V + (size_t)bh * 2048 * 64;
    const float* maskb = mask + b * 2048;

    for (int idx = tid; idx < 4096; idx += 256) Qs[idx] = Qg[idx];

    float mi[4], li[4], acc[4][4];
#pragma unroll
    for (int i = 0; i < 4; ++i) {
        mi[i] = -INFINITY; li[i] = 0.0f;
#pragma unroll
        for (int j = 0; j < 4; ++j) acc[i][j] = 0.0f;
    }

    for (int kt = 0; kt < 32; ++kt) {
        __syncthreads();   // previous tile's P/V fully consumed
        for (int idx = tid; idx < 4096; idx += 256) {
            int r = idx >> 6, d = idx & 63;
            Ks[r * 68 + d] = Kgb[(size_t)(kt * 64 + r) * 64 + d];
            Vs[r * 68 + d] = Vgb[(size_t)(kt * 64 + r) * 64 + d];
        }
        __syncthreads();

        // S = Q K^T  (rows ty*4+i, kv-cols tx+16j)
        float s[4][4];
#pragma unroll
        for (int i = 0; i < 4; ++i)
#pragma unroll
            for (int j = 0; j < 4; ++j) s[i][j] = 0.0f;

#pragma unroll
        for (int k = 0; k < 64; k += 4) {
            float4 q[4], kr[4];
#pragma unroll
            for (int i = 0; i < 4; ++i) q[i] = *(const float4*)&Qs[(ty * 4 + i) * 64 + k];
#pragma unroll
            for (int j = 0; j < 4; ++j) kr[j] = *(const float4*)&Ks[(tx + 16 * j) * 68 + k];
#pragma unroll
            for (int i = 0; i < 4; ++i)
#pragma unroll
                for (int j = 0; j < 4; ++j) {
                    s[i][j] += q[i].x * kr[j].x;
                    s[i][j] += q[i].y * kr[j].y;
                    s[i][j] += q[i].z * kr[j].z;
                    s[i][j] += q[i].w * kr[j].w;
                }
        }

        // scale + mask, online softmax update
        float mk[4];
#pragma unroll
        for (int j = 0; j < 4; ++j) mk[j] = maskb[kt * 64 + tx + 16 * j];

        float p[4][4], corr[4], rs[4];
#pragma unroll
        for (int i = 0; i < 4; ++i) {
            float rm = -INFINITY;
#pragma unroll
            for (int j = 0; j < 4; ++j) {
                s[i][j] = s[i][j] * 0.125f + mk[j];
                rm = fmaxf(rm, s[i][j]);
            }
            // butterfly max across the 16 tx lanes
            rm = fmaxf(rm, __shfl_xor_sync(0xffffffffu, rm, 8));
            rm = fmaxf(rm, __shfl_xor_sync(0xffffffffu, rm, 4));
            rm = fmaxf(rm, __shfl_xor_sync(0xffffffffu, rm, 2));
            rm = fmaxf(rm, __shfl_xor_sync(0xffffffffu, rm, 1));
            float mnew = fmaxf(mi[i], rm);
            corr[i] = __expf(mi[i] - mnew);
            float sum = 0.0f;
#pragma unroll
            for (int j = 0; j < 4; ++j) {
                p[i][j] = __expf(s[i][j] - mnew);
                sum += p[i][j];
            }
            sum += __shfl_xor_sync(0xffffffffu, sum, 8);
            sum += __shfl_xor_sync(0xffffffffu, sum, 4);
            sum += __shfl_xor_sync(0xffffffffu, sum, 2);
            sum += __shfl_xor_sync(0xffffffffu, sum, 1);
            rs[i] = sum;
            mi[i] = mnew;
        }
#pragma unroll
        for (int i = 0; i < 4; ++i) {
            li[i] = li[i] * corr[i] + rs[i];
#pragma unroll
            for (int j = 0; j < 4; ++j) acc[i][j] *= corr[i];
        }

        __syncthreads();   // everyone done reading Ks
        // write P into the K buffer
#pragma unroll
        for (int i = 0; i < 4; ++i)
#pragma unroll
            for (int j = 0; j < 4; ++j)
                Ks[(ty * 4 + i) * 68 + tx + 16 * j] = p[i][j];
        __syncthreads();

        // O += P V  (Dh-cols tx+16j)
#pragma unroll
        for (int k = 0; k < 64; k += 4) {
            float4 pr[4];
#pragma unroll
            for (int i = 0; i < 4; ++i) pr[i] = *(const float4*)&Ks[(ty * 4 + i) * 68 + k];
#pragma unroll
            for (int kk = 0; kk < 4; ++kk) {
                float vv[4];
#pragma unroll
                for (int j = 0; j < 4; ++j) vv[j] = Vs[(k + kk) * 68 + tx + 16 * j];
                float pk[4] = { kk == 0 ? pr[0].x : kk == 1 ? pr[0].y : kk == 2 ? pr[0].z : pr[0].w,
                                kk == 0 ? pr[1].x : kk == 1 ? pr[1].y : kk == 2 ? pr[1].z : pr[1].w,
                                kk == 0 ? pr[2].x : kk == 1 ? pr[2].y : kk == 2 ? pr[2].z : pr[2].w,
                                kk == 0 ? pr[3].x : kk == 1 ? pr[3].y : kk == 2 ? pr[3].z : pr[3].w };
#pragma unroll
                for (int i = 0; i < 4; ++i)
#pragma unroll
                    for (int j = 0; j < 4; ++j) acc[i][j] += pk[i] * vv[j];
            }
        }
    }

    // normalize + write to g_O [B,N,C]
#pragma unroll
    for (int i = 0; i < 4; ++i) {
        float inv = 1.0f / li[i];
        int row = q0 + ty * 4 + i;
#pragma unroll
        for (int j = 0; j < 4; ++j) {
            g_O[((size_t)(b * 2048 + row)) * 512 + h * 64 + tx + 16 * j] = acc[i][j] * inv;
        }
    }
}

// ---------------------------------------------------------------------------
// Kernel 3: output projection (M=8192, N=512, K=512) + bias
// ---------------------------------------------------------------------------
__global__ __launch_bounds__(256) void gemm_proj_kernel(const float* __restrict__ W,
                                                        const float* __restrict__ bias,
                                                        float* __restrict__ out) {
    __shared__ float As[16][132];
    __shared__ float Bs[16][132];
    int tid = threadIdx.x;
    int tx = tid & 15, ty = tid >> 4;
    int m0 = blockIdx.y * 128;
    int n0 = blockIdx.x * 128;
    int lr = tid >> 2;
    int lk = (tid & 3) << 2;

    float acc[8][8];
#pragma unroll
    for (int i = 0; i < 8; ++i)
#pragma unroll
        for (int j = 0; j < 8; ++j) acc[i][j] = 0.0f;

    for (int k0 = 0; k0 < 512; k0 += 16) {
        float4 a0 = *(const float4*)&g_O[(size_t)(m0 + lr) * 512 + k0 + lk];
        float4 a1 = *(const float4*)&g_O[(size_t)(m0 + lr + 64) * 512 + k0 + lk];
        float4 b0 = *(const float4*)&W[(size_t)(n0 + lr) * 512 + k0 + lk];
        float4 b1 = *(const float4*)&W[(size_t)(n0 + lr + 64) * 512 + k0 + lk];
        As[lk + 0][lr] = a0.x; As[lk + 1][lr] = a0.y; As[lk + 2][lr] = a0.z; As[lk + 3][lr] = a0.w;
        As[lk + 0][lr + 64] = a1.x; As[lk + 1][lr + 64] = a1.y; As[lk + 2][lr + 64] = a1.z; As[lk + 3][lr + 64] = a1.w;
        Bs[lk + 0][lr] = b0.x; Bs[lk + 1][lr] = b0.y; Bs[lk + 2][lr] = b0.z; Bs[lk + 3][lr] = b0.w;
        Bs[lk + 0][lr + 64] = b1.x; Bs[lk + 1][lr + 64] = b1.y; Bs[lk + 2][lr + 64] = b1.z; Bs[lk + 3][lr + 64] = b1.w;
        __syncthreads();
#pragma unroll
        for (int k = 0; k < 16; ++k) {
            float4 ra0 = *(const float4*)&As[k][ty * 8];
            float4 ra1 = *(const float4*)&As[k][ty * 8 + 4];
            float4 rb0 = *(const float4*)&Bs[k][tx * 4];
            float4 rb1 = *(const float4*)&Bs[k][tx * 4 + 64];
            float ra[8] = {ra0.x, ra0.y, ra0.z, ra0.w, ra1.x, ra1.y, ra1.z, ra1.w};
            float rb[8] = {rb0.x, rb0.y, rb0.z, rb0.w, rb1.x, rb1.y, rb1.z, rb1.w};
#pragma unroll
            for (int i = 0; i < 8; ++i)
#pragma unroll
                for (int j = 0; j < 8; ++j) acc[i][j] += ra[i] * rb[j];
        }
        __syncthreads();
    }

#pragma unroll
    for (int i = 0; i < 8; ++i) {
        int m = m0 + ty * 8 + i;
#pragma unroll
        for (int g = 0; g < 2; ++g) {
            int cb = n0 + tx * 4 + g * 64;
            float4 bb = *(const float4*)&bias[cb];
            float4 o;
            o.x = acc[i][g * 4 + 0] + bb.x;
            o.y = acc[i][g * 4 + 1] + bb.y;
            o.z = acc[i][g * 4 + 2] + bb.z;
            o.w = acc[i][g * 4 + 3] + bb.w;
            *(float4*)&out[(size_t)m * 512 + cb] = o;
        }
    }
}

// ---------------------------------------------------------------------------
extern "C" void kernel_launch(void* const* d_in, const int* in_sizes, int n_in,
                              void* d_out, int out_size) {
    const float* x     = (const float*)d_in[0];
    const float* mask  = (const float*)d_in[1];
    const float* times = (const float*)d_in[2];
    const float* Wqkv  = (const float*)d_in[3];
    const float* Wproj = (const float*)d_in[4];
    const float* bproj = (const float*)d_in[5];
    (void)in_sizes; (void)n_in; (void)out_size;   // num_cls_token == 0 (fixed input)

    rope_table_kernel<<<(B_ * N_ * 32 + 255) / 256, 256>>>(times);
    gemm_qkv_kernel<<<dim3(NQKV / 128, M_ / 128), 256>>>(x, Wqkv);

    const int attn_smem = (4096 + 64 * 68 + 64 * 68) * sizeof(float);  // 51200
    cudaFuncSetAttribute(attn_kernel, cudaFuncAttributeMaxDynamicSharedMemorySize, attn_smem);
    attn_kernel<<<dim3(N_ / 64, B_ * H_), 256, attn_smem>>>(mask);

    gemm_proj_kernel<<<dim3(C_ / 128, M_ / 128), 256>>>(Wproj, bproj, (float*)d_out);
}